// round 2
// baseline (speedup 1.0000x reference)
#include <cuda_runtime.h>
#include <math.h>

#define H 1024
#define M_ROWS 32768
#define BM 64
#define BN 64
#define BK 16

// Ping-pong hidden-state scratch (128 MiB each). Static __device__ globals:
// allocation-free per harness rules.
__device__ __align__(16) float g_bufA[(size_t)M_ROWS * H];
__device__ __align__(16) float g_bufB[(size_t)M_ROWS * H];

__device__ __forceinline__ float sigm(float x) { return 1.0f / (1.0f + expf(-x)); }

// Fused 3-matrix GEMM: computes acc_g[m][n] = sum_k A[m][k] * Bg[n][k] for g=0,1,2
// then applies either the GRU epilogue (MODE=0) or the highway epilogue (MODE=1).
//
// MODE 0 (initial GRU step, h0 = 0):
//   B0/B1/B2 = w_ih gate slices (r, z, n), e0 = b_ih, e1 = b_hh
//   r = sigmoid(acc0 + b_ih[n]      + b_hh[n])
//   z = sigmoid(acc1 + b_ih[H+n]    + b_hh[H+n])
//   nn= tanh   (acc2 + b_ih[2H+n]   + r * b_hh[2H+n])
//   out = (1 - z) * nn
//
// MODE 1 (micro step s):
//   B0=WH[s], B1=WT[s], B2=WC[s]; e0=bH[s], e1=bT[s], e2=bC[s]; hin = h
//   hh = tanh(acc0 + bH[n]); t = sigmoid(acc1 + bT[n]); c = sigmoid(acc2 + bC[n])
//   out = hh * t + hin * (1 - c)
template<int KTOT, int MODE>
__global__ void __launch_bounds__(256, 2)
rhn_fused3(const float* __restrict__ A,
           const float* __restrict__ B0,
           const float* __restrict__ B1,
           const float* __restrict__ B2,
           const float* __restrict__ e0,
           const float* __restrict__ e1,
           const float* __restrict__ e2,
           const float* __restrict__ hin,
           float* __restrict__ out)
{
    // k-major smem tiles, padded (+4) so transposed stores are conflict-free
    // and float4 reads stay 16B-aligned (row stride 68 floats = 272B = 17*16B).
    __shared__ __align__(16) float As[BK][BM + 4];
    __shared__ __align__(16) float Bs[3][BK][BN + 4];

    const int tid = threadIdx.x;
    const int tx = tid & 15;   // output column group (4 cols)
    const int ty = tid >> 4;   // output row group (4 rows)
    const int m0 = blockIdx.y * BM;
    const int n0 = blockIdx.x * BN;

    // Tile-load mapping: thread -> (row-in-tile, k-offset), one float4 per array.
    const int lr = tid >> 2;          // 0..63
    const int lk = (tid & 3) << 2;    // 0,4,8,12

    const float* aP  = A  + (size_t)(m0 + lr) * KTOT + lk;
    const float* b0P = B0 + (size_t)(n0 + lr) * KTOT + lk;
    const float* b1P = B1 + (size_t)(n0 + lr) * KTOT + lk;
    const float* b2P = B2 + (size_t)(n0 + lr) * KTOT + lk;

    float4 ra  = *(const float4*)aP;
    float4 rb0 = *(const float4*)b0P;
    float4 rb1 = *(const float4*)b1P;
    float4 rb2 = *(const float4*)b2P;

    float acc[3][4][4];
#pragma unroll
    for (int g = 0; g < 3; g++)
#pragma unroll
        for (int i = 0; i < 4; i++)
#pragma unroll
            for (int j = 0; j < 4; j++)
                acc[g][i][j] = 0.0f;

    const int NT = KTOT / BK;
    for (int kt = 0; kt < NT; kt++) {
        // commit prefetched tile to smem (transposed to k-major)
        As[lk + 0][lr] = ra.x;  As[lk + 1][lr] = ra.y;
        As[lk + 2][lr] = ra.z;  As[lk + 3][lr] = ra.w;
        Bs[0][lk + 0][lr] = rb0.x; Bs[0][lk + 1][lr] = rb0.y;
        Bs[0][lk + 2][lr] = rb0.z; Bs[0][lk + 3][lr] = rb0.w;
        Bs[1][lk + 0][lr] = rb1.x; Bs[1][lk + 1][lr] = rb1.y;
        Bs[1][lk + 2][lr] = rb1.z; Bs[1][lk + 3][lr] = rb1.w;
        Bs[2][lk + 0][lr] = rb2.x; Bs[2][lk + 1][lr] = rb2.y;
        Bs[2][lk + 2][lr] = rb2.z; Bs[2][lk + 3][lr] = rb2.w;
        __syncthreads();

        // prefetch next tile while computing on this one
        if (kt + 1 < NT) {
            aP += BK; b0P += BK; b1P += BK; b2P += BK;
            ra  = *(const float4*)aP;
            rb0 = *(const float4*)b0P;
            rb1 = *(const float4*)b1P;
            rb2 = *(const float4*)b2P;
        }

#pragma unroll
        for (int kk = 0; kk < BK; kk++) {
            float4 av  = *(const float4*)&As[kk][ty << 2];
            float4 bv0 = *(const float4*)&Bs[0][kk][tx << 2];
            float4 bv1 = *(const float4*)&Bs[1][kk][tx << 2];
            float4 bv2 = *(const float4*)&Bs[2][kk][tx << 2];
            float aa[4] = {av.x, av.y, av.z, av.w};
            float b0a[4] = {bv0.x, bv0.y, bv0.z, bv0.w};
            float b1a[4] = {bv1.x, bv1.y, bv1.z, bv1.w};
            float b2a[4] = {bv2.x, bv2.y, bv2.z, bv2.w};
#pragma unroll
            for (int i = 0; i < 4; i++) {
#pragma unroll
                for (int j = 0; j < 4; j++) {
                    acc[0][i][j] = fmaf(aa[i], b0a[j], acc[0][i][j]);
                    acc[1][i][j] = fmaf(aa[i], b1a[j], acc[1][i][j]);
                    acc[2][i][j] = fmaf(aa[i], b2a[j], acc[2][i][j]);
                }
            }
        }
        __syncthreads();
    }

    // ---- Epilogue ----
    const int nb = n0 + (tx << 2);

    if (MODE == 0) {
        float br[4], bz[4], bni[4], bnh[4];
#pragma unroll
        for (int j = 0; j < 4; j++) {
            int n = nb + j;
            br[j]  = e0[n]         + e1[n];
            bz[j]  = e0[H + n]     + e1[H + n];
            bni[j] = e0[2 * H + n];
            bnh[j] = e1[2 * H + n];
        }
#pragma unroll
        for (int i = 0; i < 4; i++) {
            int m = m0 + (ty << 2) + i;
            float4 o;
            float res[4];
#pragma unroll
            for (int j = 0; j < 4; j++) {
                float r  = sigm(acc[0][i][j] + br[j]);
                float z  = sigm(acc[1][i][j] + bz[j]);
                float nn = tanhf(acc[2][i][j] + bni[j] + r * bnh[j]);
                res[j] = (1.0f - z) * nn;
            }
            o.x = res[0]; o.y = res[1]; o.z = res[2]; o.w = res[3];
            *(float4*)&out[(size_t)m * H + nb] = o;
        }
    } else {
        float bh[4], bt[4], bc[4];
#pragma unroll
        for (int j = 0; j < 4; j++) {
            int n = nb + j;
            bh[j] = e0[n];
            bt[j] = e1[n];
            bc[j] = e2[n];
        }
#pragma unroll
        for (int i = 0; i < 4; i++) {
            int m = m0 + (ty << 2) + i;
            float4 hv = *(const float4*)&hin[(size_t)m * H + nb];
            float hva[4] = {hv.x, hv.y, hv.z, hv.w};
            float4 o;
            float res[4];
#pragma unroll
            for (int j = 0; j < 4; j++) {
                float hh = tanhf(acc[0][i][j] + bh[j]);
                float t  = sigm(acc[1][i][j] + bt[j]);
                float c  = sigm(acc[2][i][j] + bc[j]);
                res[j] = hh * t + hva[j] * (1.0f - c);
            }
            o.x = res[0]; o.y = res[1]; o.z = res[2]; o.w = res[3];
            *(float4*)&out[(size_t)m * H + nb] = o;
        }
    }
}

extern "C" void kernel_launch(void* const* d_in, const int* in_sizes, int n_in,
                              void* d_out, int out_size)
{
    const float* x    = (const float*)d_in[0];
    const float* w_ih = (const float*)d_in[1];
    // d_in[2] = w_hh: mathematically unused (h0 = 0)
    const float* b_ih = (const float*)d_in[3];
    const float* b_hh = (const float*)d_in[4];
    const float* WH   = (const float*)d_in[5];
    const float* bH   = (const float*)d_in[6];
    const float* WT   = (const float*)d_in[7];
    const float* bT   = (const float*)d_in[8];
    const float* WC   = (const float*)d_in[9];
    const float* bC   = (const float*)d_in[10];
    float* out = (float*)d_out;

    float *bufA, *bufB;
    cudaGetSymbolAddress((void**)&bufA, g_bufA);
    cudaGetSymbolAddress((void**)&bufB, g_bufB);

    dim3 blk(256);
    dim3 grd(H / BN, M_ROWS / BM);

    // Initial GRU gate GEMM (K = 512): x -> h  into bufA
    rhn_fused3<512, 0><<<grd, blk>>>(
        x,
        w_ih,
        w_ih + (size_t)H * 512,
        w_ih + (size_t)2 * H * 512,
        b_ih, b_hh, nullptr, nullptr,
        bufA);

    // 5 highway micro-steps (K = 1024), ping-pong; last writes d_out.
    for (int s = 0; s < 5; s++) {
        const float* hi = (s & 1) ? bufB : bufA;
        float* ho = (s == 4) ? out : ((s & 1) ? bufA : bufB);
        rhn_fused3<1024, 1><<<grd, blk>>>(
            hi,
            WH + (size_t)s * H * H,
            WT + (size_t)s * H * H,
            WC + (size_t)s * H * H,
            bH + s * H, bT + s * H, bC + s * H,
            hi,
            ho);
    }
}

// round 4
// speedup vs baseline: 2.4988x; 2.4988x over previous
#include <cuda_runtime.h>
#include <cuda_bf16.h>
#include <cstdint>

#define HID 1024
#define MROWS 32768
#define STAGE 40960
#define NSTAGE 4
#define DSMEM_TOTAL (NSTAGE * STAGE)

// ---- static device scratch (allocation-free rule) ----
__device__ __align__(16) __nv_bfloat16 g_x_hi [(size_t)MROWS * 512];
__device__ __align__(16) __nv_bfloat16 g_x_lo [(size_t)MROWS * 512];
__device__ __align__(16) __nv_bfloat16 g_w_hi [(size_t)3 * HID * 512];
__device__ __align__(16) __nv_bfloat16 g_w_lo [(size_t)3 * HID * 512];
__device__ __align__(16) __nv_bfloat16 g_WH_hi[(size_t)5 * HID * HID];
__device__ __align__(16) __nv_bfloat16 g_WH_lo[(size_t)5 * HID * HID];
__device__ __align__(16) __nv_bfloat16 g_WT_hi[(size_t)5 * HID * HID];
__device__ __align__(16) __nv_bfloat16 g_WT_lo[(size_t)5 * HID * HID];
__device__ __align__(16) __nv_bfloat16 g_WC_hi[(size_t)5 * HID * HID];
__device__ __align__(16) __nv_bfloat16 g_WC_lo[(size_t)5 * HID * HID];
__device__ __align__(16) __nv_bfloat16 g_hA_hi[(size_t)MROWS * HID];
__device__ __align__(16) __nv_bfloat16 g_hA_lo[(size_t)MROWS * HID];
__device__ __align__(16) __nv_bfloat16 g_hB_hi[(size_t)MROWS * HID];
__device__ __align__(16) __nv_bfloat16 g_hB_lo[(size_t)MROWS * HID];

// ---- helpers ----
__device__ __forceinline__ uint32_t smem_u32(const void* p) {
    uint32_t a;
    asm("{ .reg .u64 t; cvta.to.shared.u64 t, %1; cvt.u32.u64 %0, t; }" : "=r"(a) : "l"(p));
    return a;
}
__device__ __forceinline__ void cpa16(uint32_t s, const void* g) {
    asm volatile("cp.async.cg.shared.global [%0], [%1], 16;" :: "r"(s), "l"(g));
}
__device__ __forceinline__ void cpa_commit() {
    asm volatile("cp.async.commit_group;" ::: "memory");
}
__device__ __forceinline__ void cpa_wait2() {
    asm volatile("cp.async.wait_group 2;" ::: "memory");
}
__device__ __forceinline__ void ldsm4(uint32_t* r, uint32_t a) {
    asm volatile("ldmatrix.sync.aligned.m8n8.x4.shared.b16 {%0,%1,%2,%3}, [%4];"
                 : "=r"(r[0]), "=r"(r[1]), "=r"(r[2]), "=r"(r[3]) : "r"(a));
}
__device__ __forceinline__ void mma16816(float* d, const uint32_t* a, uint32_t b0, uint32_t b1) {
    asm volatile(
        "mma.sync.aligned.m16n8k16.row.col.f32.bf16.bf16.f32 "
        "{%0,%1,%2,%3}, {%4,%5,%6,%7}, {%8,%9}, {%0,%1,%2,%3};"
        : "+f"(d[0]), "+f"(d[1]), "+f"(d[2]), "+f"(d[3])
        : "r"(a[0]), "r"(a[1]), "r"(a[2]), "r"(a[3]), "r"(b0), "r"(b1));
}
// swizzled byte offset of 16B chunk (row r, chunk c in 0..3) in a k32 tile
__device__ __forceinline__ uint32_t swz(int r, int c) {
    return (uint32_t)((r >> 1) * 128 + (r & 1) * 64 + ((c ^ ((r >> 1) & 3)) << 4));
}
__device__ __forceinline__ float sigm_(float x) { return __fdividef(1.f, 1.f + __expf(-x)); }
__device__ __forceinline__ float tanh_(float x) {
    float ax = fabsf(x), e = __expf(-2.f * ax);
    float t = __fdividef(1.f - e, 1.f + e);
    return x >= 0.f ? t : -t;
}
__device__ __forceinline__ float bf2f(uint32_t b) { return __uint_as_float(b << 16); }
__device__ __forceinline__ uint32_t f2bf(float f) {
    return (uint32_t)__bfloat16_as_ushort(__float2bfloat16(f));
}

// ---- split fp32 -> (hi, lo) bf16 ----
__global__ void split4(const float4* __restrict__ src, uint2* __restrict__ hi,
                       uint2* __restrict__ lo, int n4) {
    int i = blockIdx.x * blockDim.x + threadIdx.x;
    if (i >= n4) return;
    float4 v = src[i];
    float vv[4] = {v.x, v.y, v.z, v.w};
    uint32_t h[4], l[4];
#pragma unroll
    for (int k = 0; k < 4; k++) {
        h[k] = f2bf(vv[k]);
        l[k] = f2bf(vv[k] - bf2f(h[k]));
    }
    hi[i] = make_uint2(h[0] | (h[1] << 16), h[2] | (h[3] << 16));
    lo[i] = make_uint2(l[0] | (l[1] << 16), l[2] | (l[3] << 16));
}

// ---- fused 3-gate mma.sync GEMM + epilogue ----
// Tile: M=128, N=64 per gate, 3 gates. 8 warps: wm = wid&1 (2x64 rows), wn = wid>>1 (4x16 cols).
// smem stage layout: Ahi[0,8K) Alo[8K,16K) B[16K + (g*2+term)*4K) each 64x32.
template<int KF, int MODE, int WSPLIT>
__global__ void __launch_bounds__(256, 1)
rhn_mma(const __nv_bfloat16* __restrict__ Ahi, const __nv_bfloat16* __restrict__ Alo,
        const __nv_bfloat16* __restrict__ B0hi, const __nv_bfloat16* __restrict__ B0lo,
        const __nv_bfloat16* __restrict__ B1hi, const __nv_bfloat16* __restrict__ B1lo,
        const __nv_bfloat16* __restrict__ B2hi, const __nv_bfloat16* __restrict__ B2lo,
        const float* __restrict__ e0, const float* __restrict__ e1, const float* __restrict__ e2,
        const __nv_bfloat16* __restrict__ hinHi, const __nv_bfloat16* __restrict__ hinLo,
        float* __restrict__ outF,
        __nv_bfloat16* __restrict__ outHi, __nv_bfloat16* __restrict__ outLo)
{
    constexpr int NK = KF / 32;
    extern __shared__ __align__(128) uint8_t smemraw[];
    const uint32_t sbase = smem_u32(smemraw);

    const int tid = threadIdx.x;
    const int lane = tid & 31;
    const int wm = (tid >> 5) & 1;
    const int wn = tid >> 6;
    const int m0 = blockIdx.y * 128;
    const int n0 = blockIdx.x * 64;

    // ---- producer mapping: 10 x 16B cp.async per thread per stage ----
    const int pr = tid >> 2;        // 0..63
    const int pc = tid & 3;         // 16B chunk in k32
    const char* gp[10];
    uint32_t so[10];
    {
        gp[0] = (const char*)(Ahi + (size_t)(m0 + pr) * KF + pc * 8);
        gp[1] = (const char*)(Ahi + (size_t)(m0 + pr + 64) * KF + pc * 8);
        gp[2] = (const char*)(Alo + (size_t)(m0 + pr) * KF + pc * 8);
        gp[3] = (const char*)(Alo + (size_t)(m0 + pr + 64) * KF + pc * 8);
        so[0] = swz(pr, pc);
        so[1] = swz(pr + 64, pc);
        so[2] = 8192u + swz(pr, pc);
        so[3] = 8192u + swz(pr + 64, pc);
        const __nv_bfloat16* bp[6] = {B0hi, B0lo, B1hi, B1lo, B2hi, B2lo};
#pragma unroll
        for (int t = 0; t < 6; t++) {
            gp[4 + t] = (const char*)(bp[t] + (size_t)(n0 + pr) * KF + pc * 8);
            so[4 + t] = 16384u + t * 4096u + swz(pr, pc);
        }
    }

    // ---- consumer (ldmatrix) invariants ----
    const int mat = lane >> 3;
    const int khf = lane >> 4;              // mat>>1: k-half select
    uint32_t aln[4], bln;
    int asw[4], bsw;
#pragma unroll
    for (int mi = 0; mi < 4; mi++) {
        int r = wm * 64 + mi * 16 + (mat & 1) * 8 + (lane & 7);
        aln[mi] = (uint32_t)((r >> 1) * 128 + (r & 1) * 64);
        asw[mi] = (r >> 1) & 3;
    }
    {
        int r = wn * 16 + (mat & 1) * 8 + (lane & 7);
        bln = (uint32_t)((r >> 1) * 128 + (r & 1) * 64);
        bsw = (r >> 1) & 3;
    }

    float acc[3][4][2][4];
#pragma unroll
    for (int g = 0; g < 3; g++)
#pragma unroll
        for (int mi = 0; mi < 4; mi++)
#pragma unroll
            for (int nf = 0; nf < 2; nf++)
#pragma unroll
                for (int e = 0; e < 4; e++) acc[g][mi][nf][e] = 0.f;

#define ISSUE_STAGE(CH)                                                       \
    {                                                                         \
        uint32_t sb_ = sbase + ((CH) & 3) * STAGE;                            \
        size_t go_ = (size_t)(CH) * 64;                                       \
        _Pragma("unroll")                                                     \
        for (int j = 0; j < 10; j++) cpa16(sb_ + so[j], gp[j] + go_);         \
    }

    ISSUE_STAGE(0); cpa_commit();
    ISSUE_STAGE(1); cpa_commit();
    ISSUE_STAGE(2); cpa_commit();

    for (int i = 0; i < NK; i++) {
        cpa_wait2();
        __syncthreads();
        const uint32_t sb = sbase + (i & 3) * STAGE;

#pragma unroll
        for (int ks = 0; ks < 2; ks++) {
            const int c = ks * 2 + khf;
            uint32_t aH[16], aL[16];
#pragma unroll
            for (int mi = 0; mi < 4; mi++) {
                uint32_t off = aln[mi] + (uint32_t)((c ^ asw[mi]) << 4);
                ldsm4(&aH[mi * 4], sb + off);
                ldsm4(&aL[mi * 4], sb + 8192u + off);
            }
            const uint32_t boff = bln + (uint32_t)((c ^ bsw) << 4);
#pragma unroll
            for (int g = 0; g < 3; g++) {
                uint32_t bh[4], bl[4];
                ldsm4(bh, sb + 16384u + (g * 2 + 0) * 4096u + boff);
                ldsm4(bl, sb + 16384u + (g * 2 + 1) * 4096u + boff);
#pragma unroll
                for (int mi = 0; mi < 4; mi++) {
                    mma16816(acc[g][mi][0], &aH[mi * 4], bh[0], bh[2]);
                    mma16816(acc[g][mi][1], &aH[mi * 4], bh[1], bh[3]);
                    mma16816(acc[g][mi][0], &aH[mi * 4], bl[0], bl[2]);
                    mma16816(acc[g][mi][1], &aH[mi * 4], bl[1], bl[3]);
                    mma16816(acc[g][mi][0], &aL[mi * 4], bh[0], bh[2]);
                    mma16816(acc[g][mi][1], &aL[mi * 4], bh[1], bh[3]);
                }
            }
        }
        __syncthreads();
        if (i + 3 < NK) ISSUE_STAGE(i + 3);
        cpa_commit();   // commit every iter (possibly empty) to keep wait_group accounting
    }

    // ---- epilogue ----
    float bA[2][2], bB[2][2], bC2[2][2], bD[2][2];
#pragma unroll
    for (int nf = 0; nf < 2; nf++) {
        int n = n0 + wn * 16 + nf * 8 + (lane & 3) * 2;
        if (MODE == 0) {
            float2 i0 = *(const float2*)&e0[n],        h0 = *(const float2*)&e1[n];
            float2 i1 = *(const float2*)&e0[HID + n],  h1 = *(const float2*)&e1[HID + n];
            float2 i2 = *(const float2*)&e0[2*HID + n], h2 = *(const float2*)&e1[2*HID + n];
            bA[nf][0] = i0.x + h0.x; bA[nf][1] = i0.y + h0.y;      // r bias
            bB[nf][0] = i1.x + h1.x; bB[nf][1] = i1.y + h1.y;      // z bias
            bC2[nf][0] = i2.x;       bC2[nf][1] = i2.y;            // n input bias
            bD[nf][0] = h2.x;        bD[nf][1] = h2.y;             // n hidden bias
        } else {
            float2 v0 = *(const float2*)&e0[n];
            float2 v1 = *(const float2*)&e1[n];
            float2 v2 = *(const float2*)&e2[n];
            bA[nf][0] = v0.x; bA[nf][1] = v0.y;
            bB[nf][0] = v1.x; bB[nf][1] = v1.y;
            bC2[nf][0] = v2.x; bC2[nf][1] = v2.y;
        }
    }

#pragma unroll
    for (int mi = 0; mi < 4; mi++) {
#pragma unroll
        for (int half = 0; half < 2; half++) {
            const int m = m0 + wm * 64 + mi * 16 + (lane >> 2) + half * 8;
#pragma unroll
            for (int nf = 0; nf < 2; nf++) {
                const int n = n0 + wn * 16 + nf * 8 + (lane & 3) * 2;
                float res[2];
#pragma unroll
                for (int e = 0; e < 2; e++) {
                    float a0 = acc[0][mi][nf][half * 2 + e];
                    float a1 = acc[1][mi][nf][half * 2 + e];
                    float a2 = acc[2][mi][nf][half * 2 + e];
                    if (MODE == 0) {
                        float r = sigm_(a0 + bA[nf][e]);
                        float z = sigm_(a1 + bB[nf][e]);
                        float nn = tanh_(a2 + bC2[nf][e] + r * bD[nf][e]);
                        res[e] = (1.f - z) * nn;
                    } else {
                        float hh = tanh_(a0 + bA[nf][e]);
                        float t  = sigm_(a1 + bB[nf][e]);
                        float cc = sigm_(a2 + bC2[nf][e]);
                        uint32_t hw = *(const uint32_t*)(hinHi + (size_t)m * HID + n);
                        uint32_t lw = *(const uint32_t*)(hinLo + (size_t)m * HID + n);
                        float hv = (e == 0) ? (bf2f(hw & 0xFFFFu) + bf2f(lw & 0xFFFFu))
                                            : (bf2f(hw >> 16) + bf2f(lw >> 16));
                        res[e] = hh * t + hv * (1.f - cc);
                    }
                }
                if (WSPLIT) {
                    uint32_t h0 = f2bf(res[0]), h1 = f2bf(res[1]);
                    uint32_t l0 = f2bf(res[0] - bf2f(h0)), l1 = f2bf(res[1] - bf2f(h1));
                    *(uint32_t*)(outHi + (size_t)m * HID + n) = h0 | (h1 << 16);
                    *(uint32_t*)(outLo + (size_t)m * HID + n) = l0 | (l1 << 16);
                } else {
                    *(float2*)(outF + (size_t)m * HID + n) = make_float2(res[0], res[1]);
                }
            }
        }
    }
}

extern "C" void kernel_launch(void* const* d_in, const int* in_sizes, int n_in,
                              void* d_out, int out_size)
{
    const float* x    = (const float*)d_in[0];
    const float* w_ih = (const float*)d_in[1];
    const float* b_ih = (const float*)d_in[3];
    const float* b_hh = (const float*)d_in[4];
    const float* WH   = (const float*)d_in[5];
    const float* bH   = (const float*)d_in[6];
    const float* WT   = (const float*)d_in[7];
    const float* bT   = (const float*)d_in[8];
    const float* WC   = (const float*)d_in[9];
    const float* bC   = (const float*)d_in[10];
    float* out = (float*)d_out;

    static bool attrSet = false;
    if (!attrSet) {
        cudaFuncSetAttribute(rhn_mma<512, 0, 1>,  cudaFuncAttributeMaxDynamicSharedMemorySize, DSMEM_TOTAL);
        cudaFuncSetAttribute(rhn_mma<1024, 1, 1>, cudaFuncAttributeMaxDynamicSharedMemorySize, DSMEM_TOTAL);
        cudaFuncSetAttribute(rhn_mma<1024, 1, 0>, cudaFuncAttributeMaxDynamicSharedMemorySize, DSMEM_TOTAL);
        attrSet = true;
    }

    __nv_bfloat16 *xh, *xl, *wh, *wl, *WHh, *WHl, *WTh, *WTl, *WCh, *WCl;
    __nv_bfloat16 *hAh, *hAl, *hBh, *hBl;
    cudaGetSymbolAddress((void**)&xh, g_x_hi);   cudaGetSymbolAddress((void**)&xl, g_x_lo);
    cudaGetSymbolAddress((void**)&wh, g_w_hi);   cudaGetSymbolAddress((void**)&wl, g_w_lo);
    cudaGetSymbolAddress((void**)&WHh, g_WH_hi); cudaGetSymbolAddress((void**)&WHl, g_WH_lo);
    cudaGetSymbolAddress((void**)&WTh, g_WT_hi); cudaGetSymbolAddress((void**)&WTl, g_WT_lo);
    cudaGetSymbolAddress((void**)&WCh, g_WC_hi); cudaGetSymbolAddress((void**)&WCl, g_WC_lo);
    cudaGetSymbolAddress((void**)&hAh, g_hA_hi); cudaGetSymbolAddress((void**)&hAl, g_hA_lo);
    cudaGetSymbolAddress((void**)&hBh, g_hB_hi); cudaGetSymbolAddress((void**)&hBl, g_hB_lo);

    // split-precision prep
    {
        int n4 = MROWS * 512 / 4;
        split4<<<(n4 + 255) / 256, 256>>>((const float4*)x, (uint2*)xh, (uint2*)xl, n4);
        n4 = 3 * HID * 512 / 4;
        split4<<<(n4 + 255) / 256, 256>>>((const float4*)w_ih, (uint2*)wh, (uint2*)wl, n4);
        n4 = 5 * HID * HID / 4;
        split4<<<(n4 + 255) / 256, 256>>>((const float4*)WH, (uint2*)WHh, (uint2*)WHl, n4);
        split4<<<(n4 + 255) / 256, 256>>>((const float4*)WT, (uint2*)WTh, (uint2*)WTl, n4);
        split4<<<(n4 + 255) / 256, 256>>>((const float4*)WC, (uint2*)WCh, (uint2*)WCl, n4);
    }

    dim3 grd(HID / 64, MROWS / 128);
    // GRU gate GEMM (K=512): x -> h (split) into hA
    rhn_mma<512, 0, 1><<<grd, 256, DSMEM_TOTAL>>>(
        xh, xl,
        wh, wl,
        wh + (size_t)HID * 512, wl + (size_t)HID * 512,
        wh + (size_t)2 * HID * 512, wl + (size_t)2 * HID * 512,
        b_ih, b_hh, nullptr, nullptr, nullptr,
        nullptr, hAh, hAl);

    // 5 highway micro-steps
    for (int s = 0; s < 5; s++) {
        size_t wo = (size_t)s * HID * HID;
        const __nv_bfloat16* ih = (s & 1) ? hBh : hAh;
        const __nv_bfloat16* il = (s & 1) ? hBl : hAl;
        __nv_bfloat16* oh = (s & 1) ? hAh : hBh;
        __nv_bfloat16* ol = (s & 1) ? hAl : hBl;
        if (s == 4)
            rhn_mma<1024, 1, 0><<<grd, 256, DSMEM_TOTAL>>>(
                ih, il, WHh + wo, WHl + wo, WTh + wo, WTl + wo, WCh + wo, WCl + wo,
                bH + s * HID, bT + s * HID, bC + s * HID,
                ih, il, out, nullptr, nullptr);
        else
            rhn_mma<1024, 1, 1><<<grd, 256, DSMEM_TOTAL>>>(
                ih, il, WHh + wo, WHl + wo, WTh + wo, WTl + wo, WCh + wo, WCl + wo,
                bH + s * HID, bT + s * HID, bC + s * HID,
                ih, il, nullptr, oh, ol);
    }
}